// round 13
// baseline (speedup 1.0000x reference)
#include <cuda_runtime.h>
#include <cuda_bf16.h>
#include <math.h>
#include <stdint.h>

#define BATCH 2
#define LSEQ  1024
#define DM    1024
#define DI    2048
#define NST   16
#define RK    64
#define DBC_W (RK + 2*NST)   /* 96 */
#define NL    4
#define MROWS (BATCH*LSEQ)   /* 2048 */
#define KSPLIT 8
#define SCH   64             /* scan chunk (timesteps) */

typedef __nv_bfloat16 bf16;

// ---------------- fp32 scratch ----------------------------------------------
__device__ float g_x    [MROWS*DM];
__device__ float g_dxc  [MROWS*DI*2];    // interleaved (delta, xc) pairs
__device__ float g_bc   [MROWS*32];      // interleaved (B, C) pairs per state
__device__ float g_part [KSPLIT*MROWS*DBC_W];

// ---------------- bf16 scratch ------------------------------------------------
__device__ bf16 g_xz_bf [MROWS*2*DI];
__device__ bf16 g_h_bf  [MROWS*DM];
__device__ bf16 g_xc_bf [MROWS*DI];
__device__ bf16 g_dbc_bf[MROWS*DBC_W];
__device__ bf16 g_u_bf  [MROWS*DI];
__device__ bf16 g_Win_bf [NL*2*DI*DM];
__device__ bf16 g_Wx_bf  [NL*DBC_W*DI];
__device__ bf16 g_Wdt_bf [NL*DI*RK];
__device__ bf16 g_Wout_bf[NL*DM*DI];

// ---------------- helpers ---------------------------------------------------
__device__ __forceinline__ float siluf(float v) { return v / (1.f + __expf(-v)); }
__device__ __forceinline__ float softplusf(float v) {
    return (v > 20.f) ? v : log1pf(__expf(v));
}
__device__ __forceinline__ void cp16(uint32_t s, const void* g, bool pred) {
    if (pred)
        asm volatile("cp.async.cg.shared.global [%0], [%1], 16;" :: "r"(s), "l"(g));
    else
        asm volatile("cp.async.cg.shared.global [%0], [%1], 16, 0;" :: "r"(s), "l"(g));
}

// ---------------- dual fp32 -> bf16 convert ----------------------------------
__global__ void f2bf2_k(const float4* __restrict__ s1, __nv_bfloat162* __restrict__ d1, int n41,
                        const float4* __restrict__ s2, __nv_bfloat162* __restrict__ d2, int n42) {
    int i = blockIdx.x * blockDim.x + threadIdx.x;
    int tot = n41 + n42;
    for (; i < tot; i += gridDim.x * blockDim.x) {
        if (i < n41) {
            float4 v = s1[i];
            d1[2*i]   = __floats2bfloat162_rn(v.x, v.y);
            d1[2*i+1] = __floats2bfloat162_rn(v.z, v.w);
        } else {
            int j = i - n41;
            float4 v = s2[j];
            d2[2*j]   = __floats2bfloat162_rn(v.x, v.y);
            d2[2*j+1] = __floats2bfloat162_rn(v.z, v.w);
        }
    }
}

// ---------------- RMSNorm -----------------------------------------------------
__global__ void rmsnorm_k(const float* __restrict__ xin, const float* __restrict__ w) {
    int row = blockIdx.x;
    const float4* xr = (const float4*)(xin + (size_t)row * DM);
    __shared__ float red[8];
    float4 v = xr[threadIdx.x];
    float s = v.x*v.x + v.y*v.y + v.z*v.z + v.w*v.w;
#pragma unroll
    for (int off = 16; off > 0; off >>= 1) s += __shfl_xor_sync(0xffffffffu, s, off);
    if ((threadIdx.x & 31) == 0) red[threadIdx.x >> 5] = s;
    __syncthreads();
    float tot = red[0] + red[1] + red[2] + red[3] + red[4] + red[5] + red[6] + red[7];
    float inv = rsqrtf(tot * (1.f / DM) + 1e-5f);
    const float4 wv = ((const float4*)w)[threadIdx.x];
    __nv_bfloat162* hr = (__nv_bfloat162*)(g_h_bf + (size_t)row * DM);
    hr[2*threadIdx.x]   = __floats2bfloat162_rn(v.x * inv * wv.x, v.y * inv * wv.y);
    hr[2*threadIdx.x+1] = __floats2bfloat162_rn(v.z * inv * wv.z, v.w * inv * wv.w);
}

// ---------------- bf16 tensor-core NT GEMM (M-tile 128) ----------------------
// epi: 0 fp32 plain, 2 fp32 acc+resid, 3 bf16 plain,
//      5 softplus(acc+bias[n]) -> stride-2 store into pair buffer slot 0
#define STAGEB 32768u
__global__ __launch_bounds__(256, 2) void bf16gemm_nt_k(
    const bf16* __restrict__ A, int lda,
    const bf16* __restrict__ B, int ldb,
    void* __restrict__ Cv, int ldc,
    const float* __restrict__ bias,
    const float* __restrict__ resid,
    int M, int N, int K, int epi,
    int kspan, size_t cspan)
{
    extern __shared__ char smem[];
    A += (size_t)blockIdx.z * kspan;
    B += (size_t)blockIdx.z * kspan;

    const int tid  = threadIdx.x;
    const int warp = tid >> 5;
    const int lane = tid & 31;
    const int m0 = blockIdx.y * 128;
    const int n0 = blockIdx.x * 128;
    const int wm = (warp >> 2) * 64;
    const int wn = (warp & 3) * 32;

    float c[4][4][4];
#pragma unroll
    for (int i = 0; i < 4; i++)
#pragma unroll
        for (int j = 0; j < 4; j++)
#pragma unroll
            for (int r = 0; r < 4; r++) c[i][j][r] = 0.f;

    const uint32_t sbase = (uint32_t)__cvta_generic_to_shared(smem);
    const int nk = K >> 6;
    const int lane8 = lane & 7;
    const int lmat  = lane >> 3;

    {
#pragma unroll
        for (int i = 0; i < 4; i++) {
            int idx = tid + i * 256;
            int r = idx >> 3, cc = idx & 7;
            uint32_t so = (uint32_t)((r << 7) + ((cc ^ (r & 7)) << 4));
            cp16(sbase + so,          A + (size_t)(m0 + r) * lda + cc * 8, (m0 + r) < M);
            cp16(sbase + 16384u + so, B + (size_t)(n0 + r) * ldb + cc * 8, (n0 + r) < N);
        }
        asm volatile("cp.async.commit_group;" ::: "memory");
    }

    for (int kt = 0; kt < nk; kt++) {
        const uint32_t st = (uint32_t)(kt & 1) * STAGEB;
        if (kt + 1 < nk) {
            const int k0 = (kt + 1) << 6;
            const uint32_t st1 = (uint32_t)((kt + 1) & 1) * STAGEB;
#pragma unroll
            for (int i = 0; i < 4; i++) {
                int idx = tid + i * 256;
                int r = idx >> 3, cc = idx & 7;
                uint32_t so = st1 + (uint32_t)((r << 7) + ((cc ^ (r & 7)) << 4));
                cp16(sbase + so,          A + (size_t)(m0 + r) * lda + k0 + cc * 8, (m0 + r) < M);
                cp16(sbase + 16384u + so, B + (size_t)(n0 + r) * ldb + k0 + cc * 8, (n0 + r) < N);
            }
            asm volatile("cp.async.commit_group;" ::: "memory");
            asm volatile("cp.async.wait_group 1;" ::: "memory");
        } else {
            asm volatile("cp.async.wait_group 0;" ::: "memory");
        }
        __syncthreads();

        const uint32_t sA = sbase + st;
        const uint32_t sB = sA + 16384u;

#pragma unroll
        for (int ks = 0; ks < 4; ks++) {
            uint32_t a[4][4];
#pragma unroll
            for (int mt = 0; mt < 4; mt++) {
                int ar = wm + mt * 16 + ((lmat & 1) << 3) + lane8;
                int ac = (ks << 1) + (lmat >> 1);
                uint32_t addr = sA + (uint32_t)((ar << 7) + ((ac ^ (ar & 7)) << 4));
                asm volatile("ldmatrix.sync.aligned.m8n8.x4.shared.b16 {%0,%1,%2,%3}, [%4];"
                             : "=r"(a[mt][0]), "=r"(a[mt][1]),
                               "=r"(a[mt][2]), "=r"(a[mt][3]) : "r"(addr));
            }
            uint32_t b[4][2];
#pragma unroll
            for (int np = 0; np < 2; np++) {
                int br = wn + np * 16 + ((lmat >> 1) << 3) + lane8;
                int bc = (ks << 1) + (lmat & 1);
                uint32_t addr = sB + (uint32_t)((br << 7) + ((bc ^ (br & 7)) << 4));
                asm volatile("ldmatrix.sync.aligned.m8n8.x4.shared.b16 {%0,%1,%2,%3}, [%4];"
                             : "=r"(b[np*2][0]), "=r"(b[np*2][1]),
                               "=r"(b[np*2+1][0]), "=r"(b[np*2+1][1]) : "r"(addr));
            }
#pragma unroll
            for (int mt = 0; mt < 4; mt++)
#pragma unroll
                for (int nt = 0; nt < 4; nt++) {
                    asm volatile(
                        "mma.sync.aligned.m16n8k16.row.col.f32.bf16.bf16.f32 "
                        "{%0,%1,%2,%3}, {%4,%5,%6,%7}, {%8,%9}, {%0,%1,%2,%3};"
                        : "+f"(c[mt][nt][0]), "+f"(c[mt][nt][1]),
                          "+f"(c[mt][nt][2]), "+f"(c[mt][nt][3])
                        : "r"(a[mt][0]), "r"(a[mt][1]), "r"(a[mt][2]), "r"(a[mt][3]),
                          "r"(b[nt][0]), "r"(b[nt][1]));
                }
        }
        __syncthreads();
    }

    // ---- epilogue ----
    float* C = (float*)Cv + (size_t)blockIdx.z * cspan;
    bf16*  Cb = (bf16*)Cv;
#pragma unroll
    for (int mt = 0; mt < 4; mt++) {
#pragma unroll
        for (int nt = 0; nt < 4; nt++) {
            int m = m0 + wm + mt * 16 + (lane >> 2);
            int n = n0 + wn + nt * 8 + 2 * (lane & 3);
#pragma unroll
            for (int half = 0; half < 2; half++) {
                int mm = m + half * 8;
                if (mm >= M || n >= N) continue;
                float v0 = c[mt][nt][half * 2];
                float v1 = c[mt][nt][half * 2 + 1];
                if (epi == 3) {
                    *(__nv_bfloat162*)(Cb + (size_t)mm * ldc + n) =
                        __floats2bfloat162_rn(v0, v1);
                    continue;
                }
                if (epi == 5) {
                    float* Cp = (float*)Cv;
                    Cp[((size_t)mm * ldc + n) * 2]     = softplusf(v0 + bias[n]);
                    Cp[((size_t)mm * ldc + n + 1) * 2] = softplusf(v1 + bias[n + 1]);
                    continue;
                }
                if (epi == 2) {
                    const float2 rv = *(const float2*)(resid + (size_t)mm * ldc + n);
                    v0 += rv.x; v1 += rv.y;
                }
                *(float2*)(C + (size_t)mm * ldc + n) = make_float2(v0, v1);
            }
        }
    }
}

// ---------------- bf16 tensor-core NT GEMM (M-tile 64, for GEMM4) ------------
// epi: 2 only (fp32 acc + resid). Grid: (N/128, M/64). 8 warps, warp tile 32x32.
#define STAGE64B 24576u
__global__ __launch_bounds__(256, 2) void bf16gemm64_nt_k(
    const bf16* __restrict__ A, int lda,
    const bf16* __restrict__ B, int ldb,
    float* __restrict__ C, int ldc,
    const float* __restrict__ resid,
    int M, int N, int K)
{
    extern __shared__ char smem[];

    const int tid  = threadIdx.x;
    const int warp = tid >> 5;
    const int lane = tid & 31;
    const int m0 = blockIdx.y * 64;
    const int n0 = blockIdx.x * 128;
    const int wm = (warp >> 2) * 32;
    const int wn = (warp & 3) * 32;

    float c[2][4][4];
#pragma unroll
    for (int i = 0; i < 2; i++)
#pragma unroll
        for (int j = 0; j < 4; j++)
#pragma unroll
            for (int r = 0; r < 4; r++) c[i][j][r] = 0.f;

    const uint32_t sbase = (uint32_t)__cvta_generic_to_shared(smem);
    const int nk = K >> 6;
    const int lane8 = lane & 7;
    const int lmat  = lane >> 3;

    {
        // A: 64 rows x 8 chunks = 512; B: 128 rows x 8 = 1024
#pragma unroll
        for (int i = 0; i < 2; i++) {
            int idx = tid + i * 256;
            int r = idx >> 3, cc = idx & 7;
            uint32_t so = (uint32_t)((r << 7) + ((cc ^ (r & 7)) << 4));
            cp16(sbase + so, A + (size_t)(m0 + r) * lda + cc * 8, (m0 + r) < M);
        }
#pragma unroll
        for (int i = 0; i < 4; i++) {
            int idx = tid + i * 256;
            int r = idx >> 3, cc = idx & 7;
            uint32_t so = (uint32_t)((r << 7) + ((cc ^ (r & 7)) << 4));
            cp16(sbase + 8192u + so, B + (size_t)(n0 + r) * ldb + cc * 8, (n0 + r) < N);
        }
        asm volatile("cp.async.commit_group;" ::: "memory");
    }

    for (int kt = 0; kt < nk; kt++) {
        const uint32_t st = (uint32_t)(kt & 1) * STAGE64B;
        if (kt + 1 < nk) {
            const int k0 = (kt + 1) << 6;
            const uint32_t st1 = (uint32_t)((kt + 1) & 1) * STAGE64B;
#pragma unroll
            for (int i = 0; i < 2; i++) {
                int idx = tid + i * 256;
                int r = idx >> 3, cc = idx & 7;
                uint32_t so = st1 + (uint32_t)((r << 7) + ((cc ^ (r & 7)) << 4));
                cp16(sbase + so, A + (size_t)(m0 + r) * lda + k0 + cc * 8, (m0 + r) < M);
            }
#pragma unroll
            for (int i = 0; i < 4; i++) {
                int idx = tid + i * 256;
                int r = idx >> 3, cc = idx & 7;
                uint32_t so = st1 + (uint32_t)((r << 7) + ((cc ^ (r & 7)) << 4));
                cp16(sbase + 8192u + so, B + (size_t)(n0 + r) * ldb + k0 + cc * 8, (n0 + r) < N);
            }
            asm volatile("cp.async.commit_group;" ::: "memory");
            asm volatile("cp.async.wait_group 1;" ::: "memory");
        } else {
            asm volatile("cp.async.wait_group 0;" ::: "memory");
        }
        __syncthreads();

        const uint32_t sA = sbase + st;
        const uint32_t sB = sA + 8192u;

#pragma unroll
        for (int ks = 0; ks < 4; ks++) {
            uint32_t a[2][4];
#pragma unroll
            for (int mt = 0; mt < 2; mt++) {
                int ar = wm + mt * 16 + ((lmat & 1) << 3) + lane8;
                int ac = (ks << 1) + (lmat >> 1);
                uint32_t addr = sA + (uint32_t)((ar << 7) + ((ac ^ (ar & 7)) << 4));
                asm volatile("ldmatrix.sync.aligned.m8n8.x4.shared.b16 {%0,%1,%2,%3}, [%4];"
                             : "=r"(a[mt][0]), "=r"(a[mt][1]),
                               "=r"(a[mt][2]), "=r"(a[mt][3]) : "r"(addr));
            }
            uint32_t b[4][2];
#pragma unroll
            for (int np = 0; np < 2; np++) {
                int br = wn + np * 16 + ((lmat >> 1) << 3) + lane8;
                int bc = (ks << 1) + (lmat & 1);
                uint32_t addr = sB + (uint32_t)((br << 7) + ((bc ^ (br & 7)) << 4));
                asm volatile("ldmatrix.sync.aligned.m8n8.x4.shared.b16 {%0,%1,%2,%3}, [%4];"
                             : "=r"(b[np*2][0]), "=r"(b[np*2][1]),
                               "=r"(b[np*2+1][0]), "=r"(b[np*2+1][1]) : "r"(addr));
            }
#pragma unroll
            for (int mt = 0; mt < 2; mt++)
#pragma unroll
                for (int nt = 0; nt < 4; nt++) {
                    asm volatile(
                        "mma.sync.aligned.m16n8k16.row.col.f32.bf16.bf16.f32 "
                        "{%0,%1,%2,%3}, {%4,%5,%6,%7}, {%8,%9}, {%0,%1,%2,%3};"
                        : "+f"(c[mt][nt][0]), "+f"(c[mt][nt][1]),
                          "+f"(c[mt][nt][2]), "+f"(c[mt][nt][3])
                        : "r"(a[mt][0]), "r"(a[mt][1]), "r"(a[mt][2]), "r"(a[mt][3]),
                          "r"(b[nt][0]), "r"(b[nt][1]));
                }
        }
        __syncthreads();
    }

    // ---- epilogue: fused residual ----
#pragma unroll
    for (int mt = 0; mt < 2; mt++) {
#pragma unroll
        for (int nt = 0; nt < 4; nt++) {
            int m = m0 + wm + mt * 16 + (lane >> 2);
            int n = n0 + wn + nt * 8 + 2 * (lane & 3);
#pragma unroll
            for (int half = 0; half < 2; half++) {
                int mm = m + half * 8;
                if (mm >= M || n >= N) continue;
                float v0 = c[mt][nt][half * 2];
                float v1 = c[mt][nt][half * 2 + 1];
                const float2 rv = *(const float2*)(resid + (size_t)mm * ldc + n);
                *(float2*)(C + (size_t)mm * ldc + n) = make_float2(v0 + rv.x, v1 + rv.y);
            }
        }
    }
}

// ---------------- split-K reduction for GEMM2 --------------------------------
__global__ void reduce_part_k() {
    int i = blockIdx.x * blockDim.x + threadIdx.x;
    if (i >= MROWS * DBC_W) return;
    float s = 0.f;
#pragma unroll
    for (int p = 0; p < KSPLIT; p++) s += g_part[(size_t)p * MROWS * DBC_W + i];
    int row = i / DBC_W, col = i % DBC_W;
    if (col < RK) {
        g_dbc_bf[i] = __float2bfloat16(s);
    } else if (col < RK + NST) {
        g_bc[(size_t)row * 32 + (col - RK) * 2] = s;
    } else {
        g_bc[(size_t)row * 32 + (col - RK - NST) * 2 + 1] = s;
    }
}

// ---------------- causal depthwise conv1d (k=4) + SiLU, 2-wide ---------------
__global__ void conv_silu_k(const float* __restrict__ cw, const float* __restrict__ cb) {
    int idx = blockIdx.x * blockDim.x + threadIdx.x;
    if (idx >= MROWS * DI / 2) return;
    int d2 = idx % (DI / 2);
    int d = d2 * 2;
    int l = (idx / (DI / 2)) % LSEQ;
    int b = idx / ((DI / 2) * LSEQ);
    float ax = cb[d], ay = cb[d + 1];
#pragma unroll
    for (int k = 0; k < 4; k++) {
        int ls = l - 3 + k;
        if (ls >= 0) {
            __nv_bfloat162 xv = *(const __nv_bfloat162*)
                (g_xz_bf + ((size_t)(b * LSEQ + ls)) * (2 * DI) + d);
            ax = fmaf(__bfloat162float(xv.x), cw[d * 4 + k], ax);
            ay = fmaf(__bfloat162float(xv.y), cw[(d + 1) * 4 + k], ay);
        }
    }
    float vx = siluf(ax), vy = siluf(ay);
    size_t e = (size_t)idx * 2;
    g_dxc[e * 2 + 1] = vx;
    g_dxc[e * 2 + 3] = vy;
    *(__nv_bfloat162*)(g_xc_bf + e) = __floats2bfloat162_rn(vx, vy);
}

// ---------------- selective scan: paired-operand smem pipeline ---------------
__device__ __forceinline__ void scan_fill(uint32_t sdx, uint32_t sbc, uint32_t sz,
                                          int tid, size_t bL, int l0, int d0) {
#pragma unroll
    for (int i = 0; i < 2; i++) {
        int idx = tid + i * 256;
        int r = idx >> 3, sg = idx & 7;
        cp16(sdx + (uint32_t)(r * 128 + sg * 16),
             g_dxc + ((bL + l0 + r) * DI + d0) * 2 + sg * 4, true);
    }
#pragma unroll
    for (int i = 0; i < 2; i++) {
        int idx = tid + i * 256;
        int r = idx >> 3, sg = idx & 7;
        cp16(sbc + (uint32_t)(r * 128 + sg * 16),
             g_bc + (bL + l0 + r) * 32 + sg * 4, true);
    }
    if (tid < 128) {
        int r = tid >> 1, sg = tid & 1;
        cp16(sz + (uint32_t)(r * 32 + sg * 16),
             g_xz_bf + (bL + l0 + r) * (2 * DI) + DI + d0 + sg * 8, true);
    }
}

__global__ __launch_bounds__(256) void scan_k(const float* __restrict__ A_log,
                                              const float* __restrict__ Dw) {
    __shared__ float s_dx[2][SCH * 32];
    __shared__ float s_bc[2][SCH * 32];
    __shared__ bf16  s_z [2][SCH * 16];
    __shared__ float s_y [SCH * 16];

    const int tid = threadIdx.x;
    const int n = tid & 15;
    const int g = tid >> 4;
    const int b  = blockIdx.x >> 7;
    const int d0 = (blockIdx.x & 127) << 4;
    const int d  = d0 + g;
    const size_t bL = (size_t)b * LSEQ;

    const float A  = -__expf(A_log[d * NST + n]);
    const float Dd = Dw[d];
    float h = 0.f;

    const uint32_t adx0 = (uint32_t)__cvta_generic_to_shared(&s_dx[0][0]);
    const uint32_t adx1 = (uint32_t)__cvta_generic_to_shared(&s_dx[1][0]);
    const uint32_t abc0 = (uint32_t)__cvta_generic_to_shared(&s_bc[0][0]);
    const uint32_t abc1 = (uint32_t)__cvta_generic_to_shared(&s_bc[1][0]);
    const uint32_t az0  = (uint32_t)__cvta_generic_to_shared(&s_z[0][0]);
    const uint32_t az1  = (uint32_t)__cvta_generic_to_shared(&s_z[1][0]);

    scan_fill(adx0, abc0, az0, tid, bL, 0, d0);
    asm volatile("cp.async.commit_group;" ::: "memory");

    const int NCH = LSEQ / SCH;
    for (int c = 0; c < NCH; c++) {
        const int buf = c & 1;
        if (c + 1 < NCH) {
            if (buf == 0) scan_fill(adx1, abc1, az1, tid, bL, (c + 1) * SCH, d0);
            else          scan_fill(adx0, abc0, az0, tid, bL, (c + 1) * SCH, d0);
            asm volatile("cp.async.commit_group;" ::: "memory");
            asm volatile("cp.async.wait_group 1;" ::: "memory");
        } else {
            asm volatile("cp.async.wait_group 0;" ::: "memory");
        }
        __syncthreads();

        const float* dx_ = s_dx[buf];
        const float* bc_ = s_bc[buf];

#pragma unroll 4
        for (int l = 0; l < SCH; l++) {
            float2 dx = *(const float2*)(dx_ + l * 32 + g * 2);   // (dt, xc)
            float2 bc = *(const float2*)(bc_ + l * 32 + n * 2);   // (B, C)

            h = fmaf(__expf(dx.x * A), h, dx.x * dx.y * bc.x);

            float y = h * bc.y;
            y += __shfl_xor_sync(0xffffffffu, y, 8);
            y += __shfl_xor_sync(0xffffffffu, y, 4);
            y += __shfl_xor_sync(0xffffffffu, y, 2);
            y += __shfl_xor_sync(0xffffffffu, y, 1);

            if (n == 0) s_y[l * 16 + g] = fmaf(Dd, dx.y, y);
        }
        __syncthreads();

        const bf16* z_ = s_z[buf];
        const int l0 = c * SCH;
#pragma unroll
        for (int i = tid; i < SCH * 16; i += 256) {
            int r = i >> 4, gg = i & 15;
            float zv = __bfloat162float(z_[i]);
            g_u_bf[(bL + l0 + r) * DI + d0 + gg] =
                __float2bfloat16(s_y[i] * siluf(zv));
        }
    }
}

// ---------------- host orchestration ----------------------------------------
extern "C" void kernel_launch(void* const* d_in, const int* in_sizes, int n_in,
                              void* d_out, int out_size) {
    const float* x      = (const float*)d_in[0];
    const float* norm_w = (const float*)d_in[1];
    const float* W_in   = (const float*)d_in[2];
    const float* conv_w = (const float*)d_in[3];
    const float* conv_b = (const float*)d_in[4];
    const float* W_x    = (const float*)d_in[5];
    const float* W_dt   = (const float*)d_in[6];
    const float* b_dt   = (const float*)d_in[7];
    const float* A_log  = (const float*)d_in[8];
    const float* Dpar   = (const float*)d_in[9];
    const float* W_out  = (const float*)d_in[10];
    float* out = (float*)d_out;

    float *px, *ppart, *pdxc;
    bf16 *pxz_bf, *ph_bf, *pxc_bf, *pdbc_bf, *pu_bf, *pWin, *pWx, *pWdt, *pWout;
    cudaGetSymbolAddress((void**)&px,     g_x);
    cudaGetSymbolAddress((void**)&ppart,  g_part);
    cudaGetSymbolAddress((void**)&pdxc,   g_dxc);
    cudaGetSymbolAddress((void**)&pxz_bf, g_xz_bf);
    cudaGetSymbolAddress((void**)&ph_bf,  g_h_bf);
    cudaGetSymbolAddress((void**)&pxc_bf, g_xc_bf);
    cudaGetSymbolAddress((void**)&pdbc_bf,g_dbc_bf);
    cudaGetSymbolAddress((void**)&pu_bf,  g_u_bf);
    cudaGetSymbolAddress((void**)&pWin,   g_Win_bf);
    cudaGetSymbolAddress((void**)&pWx,    g_Wx_bf);
    cudaGetSymbolAddress((void**)&pWdt,   g_Wdt_bf);
    cudaGetSymbolAddress((void**)&pWout,  g_Wout_bf);

    const int M = MROWS;
    const int GSMEM   = 2 * (int)STAGEB;
    const int GSMEM64 = 2 * (int)STAGE64B;
    cudaFuncSetAttribute(bf16gemm_nt_k,
                         cudaFuncAttributeMaxDynamicSharedMemorySize, GSMEM);
    cudaFuncSetAttribute(bf16gemm64_nt_k,
                         cudaFuncAttributeMaxDynamicSharedMemorySize, GSMEM64);

    dim3 thr(256);

    f2bf2_k<<<1480, 256>>>((const float4*)W_in,  (__nv_bfloat162*)pWin,  NL * 2 * DI * DM / 4,
                           (const float4*)W_x,   (__nv_bfloat162*)pWx,   NL * DBC_W * DI / 4);
    f2bf2_k<<<1480, 256>>>((const float4*)W_dt,  (__nv_bfloat162*)pWdt,  NL * DI * RK / 4,
                           (const float4*)W_out, (__nv_bfloat162*)pWout, NL * DM * DI / 4);

    for (int l = 0; l < NL; l++) {
        const float* xres = (l == 0) ? x : px;

        rmsnorm_k<<<M, 256>>>(xres, norm_w + (size_t)l * DM);

        // 2) xz = h @ W_in^T -> bf16
        {
            dim3 g(2 * DI / 128, M / 128, 1);
            bf16gemm_nt_k<<<g, thr, GSMEM>>>(ph_bf, DM, pWin + (size_t)l * 2 * DI * DM, DM,
                                             pxz_bf, 2 * DI, nullptr, nullptr,
                                             M, 2 * DI, DM, 3, 0, 0);
        }

        conv_silu_k<<<(MROWS*DI/2 + 255) / 256, 256>>>(
            conv_w + (size_t)l * DI * 4, conv_b + (size_t)l * DI);

        // 4) dbc = xc @ W_x^T  split-K=8 + reduce (dt_low bf16 + (B,C) pairs)
        {
            const int Kc = DI / KSPLIT;
            dim3 g(1, M / 128, KSPLIT);
            bf16gemm_nt_k<<<g, thr, GSMEM>>>(pxc_bf, DI, pWx + (size_t)l * DBC_W * DI, DI,
                                             ppart, DBC_W, nullptr, nullptr,
                                             M, DBC_W, Kc, 0,
                                             Kc, (size_t)M * DBC_W);
            reduce_part_k<<<(MROWS * DBC_W + 255) / 256, 256>>>();
        }

        // 5) delta = softplus(dt_low @ W_dt^T + b_dt) -> pair slot 0 of g_dxc
        {
            dim3 g(DI / 128, M / 128, 1);
            bf16gemm_nt_k<<<g, thr, GSMEM>>>(pdbc_bf, DBC_W, pWdt + (size_t)l * DI * RK, RK,
                                             pdxc, DI, b_dt + (size_t)l * DI, nullptr,
                                             M, DI, RK, 5, 0, 0);
        }

        // 6) selective scan
        scan_k<<<BATCH * (DI / 16), 256>>>(
            A_log + (size_t)l * DI * NST, Dpar + (size_t)l * DI);

        // 7) x_next = xres + u @ W_out^T  (M-tile 64: grid 256 CTAs)
        {
            float* Cout = (l == NL - 1) ? out : px;
            dim3 g(DM / 128, M / 64, 1);
            bf16gemm64_nt_k<<<g, thr, GSMEM64>>>(pu_bf, DI, pWout + (size_t)l * DM * DI, DI,
                                                 Cout, DM, xres, M, DM, DI);
        }
    }
}

// round 14
// speedup vs baseline: 1.0478x; 1.0478x over previous
#include <cuda_runtime.h>
#include <cuda_bf16.h>
#include <math.h>
#include <stdint.h>

#define BATCH 2
#define LSEQ  1024
#define DM    1024
#define DI    2048
#define NST   16
#define RK    64
#define DBC_W (RK + 2*NST)   /* 96 */
#define NL    4
#define MROWS (BATCH*LSEQ)   /* 2048 */
#define KSPLIT 8
#define SCH   64             /* scan chunk (timesteps) */

typedef __nv_bfloat16 bf16;

// ---------------- fp32 scratch ----------------------------------------------
__device__ float g_x    [MROWS*DM];
__device__ float g_dxc  [MROWS*DI*2];    // interleaved (delta, xc) pairs
__device__ float g_bc   [MROWS*32];      // interleaved (B, C) pairs per state
__device__ float g_part [KSPLIT*MROWS*DBC_W];

// ---------------- bf16 scratch ------------------------------------------------
__device__ bf16 g_xz_bf [MROWS*2*DI];
__device__ bf16 g_h_bf  [MROWS*DM];
__device__ bf16 g_xc_bf [MROWS*DI];
__device__ bf16 g_dbc_bf[MROWS*DBC_W];
__device__ bf16 g_u_bf  [MROWS*DI];
__device__ bf16 g_Win_bf [NL*2*DI*DM];
__device__ bf16 g_Wx_bf  [NL*DBC_W*DI];
__device__ bf16 g_Wdt_bf [NL*DI*RK];
__device__ bf16 g_Wout_bf[NL*DM*DI];

// ---------------- helpers ---------------------------------------------------
__device__ __forceinline__ float siluf(float v) { return v / (1.f + __expf(-v)); }
__device__ __forceinline__ float softplusf(float v) {
    return (v > 20.f) ? v : log1pf(__expf(v));
}
__device__ __forceinline__ void cp16(uint32_t s, const void* g, bool pred) {
    if (pred)
        asm volatile("cp.async.cg.shared.global [%0], [%1], 16;" :: "r"(s), "l"(g));
    else
        asm volatile("cp.async.cg.shared.global [%0], [%1], 16, 0;" :: "r"(s), "l"(g));
}

// ---------------- dual fp32 -> bf16 convert ----------------------------------
__global__ void f2bf2_k(const float4* __restrict__ s1, __nv_bfloat162* __restrict__ d1, int n41,
                        const float4* __restrict__ s2, __nv_bfloat162* __restrict__ d2, int n42) {
    int i = blockIdx.x * blockDim.x + threadIdx.x;
    int tot = n41 + n42;
    for (; i < tot; i += gridDim.x * blockDim.x) {
        if (i < n41) {
            float4 v = s1[i];
            d1[2*i]   = __floats2bfloat162_rn(v.x, v.y);
            d1[2*i+1] = __floats2bfloat162_rn(v.z, v.w);
        } else {
            int j = i - n41;
            float4 v = s2[j];
            d2[2*j]   = __floats2bfloat162_rn(v.x, v.y);
            d2[2*j+1] = __floats2bfloat162_rn(v.z, v.w);
        }
    }
}

// ---------------- RMSNorm -----------------------------------------------------
__global__ void rmsnorm_k(const float* __restrict__ xin, const float* __restrict__ w) {
    int row = blockIdx.x;
    const float4* xr = (const float4*)(xin + (size_t)row * DM);
    __shared__ float red[8];
    float4 v = xr[threadIdx.x];
    float s = v.x*v.x + v.y*v.y + v.z*v.z + v.w*v.w;
#pragma unroll
    for (int off = 16; off > 0; off >>= 1) s += __shfl_xor_sync(0xffffffffu, s, off);
    if ((threadIdx.x & 31) == 0) red[threadIdx.x >> 5] = s;
    __syncthreads();
    float tot = red[0] + red[1] + red[2] + red[3] + red[4] + red[5] + red[6] + red[7];
    float inv = rsqrtf(tot * (1.f / DM) + 1e-5f);
    const float4 wv = ((const float4*)w)[threadIdx.x];
    __nv_bfloat162* hr = (__nv_bfloat162*)(g_h_bf + (size_t)row * DM);
    hr[2*threadIdx.x]   = __floats2bfloat162_rn(v.x * inv * wv.x, v.y * inv * wv.y);
    hr[2*threadIdx.x+1] = __floats2bfloat162_rn(v.z * inv * wv.z, v.w * inv * wv.w);
}

// ---------------- bf16 tensor-core NT GEMM (M-tile 128) ----------------------
// epi: 0 fp32 plain, 2 fp32 acc+resid, 3 bf16 plain,
//      5 softplus(acc+bias[n]) -> stride-2 store into pair buffer slot 0
#define STAGEB 32768u
__global__ __launch_bounds__(256, 2) void bf16gemm_nt_k(
    const bf16* __restrict__ A, int lda,
    const bf16* __restrict__ B, int ldb,
    void* __restrict__ Cv, int ldc,
    const float* __restrict__ bias,
    const float* __restrict__ resid,
    int M, int N, int K, int epi,
    int kspan, size_t cspan)
{
    extern __shared__ char smem[];
    A += (size_t)blockIdx.z * kspan;
    B += (size_t)blockIdx.z * kspan;

    const int tid  = threadIdx.x;
    const int warp = tid >> 5;
    const int lane = tid & 31;
    const int m0 = blockIdx.y * 128;
    const int n0 = blockIdx.x * 128;
    const int wm = (warp >> 2) * 64;
    const int wn = (warp & 3) * 32;

    float c[4][4][4];
#pragma unroll
    for (int i = 0; i < 4; i++)
#pragma unroll
        for (int j = 0; j < 4; j++)
#pragma unroll
            for (int r = 0; r < 4; r++) c[i][j][r] = 0.f;

    const uint32_t sbase = (uint32_t)__cvta_generic_to_shared(smem);
    const int nk = K >> 6;
    const int lane8 = lane & 7;
    const int lmat  = lane >> 3;

    {
#pragma unroll
        for (int i = 0; i < 4; i++) {
            int idx = tid + i * 256;
            int r = idx >> 3, cc = idx & 7;
            uint32_t so = (uint32_t)((r << 7) + ((cc ^ (r & 7)) << 4));
            cp16(sbase + so,          A + (size_t)(m0 + r) * lda + cc * 8, (m0 + r) < M);
            cp16(sbase + 16384u + so, B + (size_t)(n0 + r) * ldb + cc * 8, (n0 + r) < N);
        }
        asm volatile("cp.async.commit_group;" ::: "memory");
    }

    for (int kt = 0; kt < nk; kt++) {
        const uint32_t st = (uint32_t)(kt & 1) * STAGEB;
        if (kt + 1 < nk) {
            const int k0 = (kt + 1) << 6;
            const uint32_t st1 = (uint32_t)((kt + 1) & 1) * STAGEB;
#pragma unroll
            for (int i = 0; i < 4; i++) {
                int idx = tid + i * 256;
                int r = idx >> 3, cc = idx & 7;
                uint32_t so = st1 + (uint32_t)((r << 7) + ((cc ^ (r & 7)) << 4));
                cp16(sbase + so,          A + (size_t)(m0 + r) * lda + k0 + cc * 8, (m0 + r) < M);
                cp16(sbase + 16384u + so, B + (size_t)(n0 + r) * ldb + k0 + cc * 8, (n0 + r) < N);
            }
            asm volatile("cp.async.commit_group;" ::: "memory");
            asm volatile("cp.async.wait_group 1;" ::: "memory");
        } else {
            asm volatile("cp.async.wait_group 0;" ::: "memory");
        }
        __syncthreads();

        const uint32_t sA = sbase + st;
        const uint32_t sB = sA + 16384u;

#pragma unroll
        for (int ks = 0; ks < 4; ks++) {
            uint32_t a[4][4];
#pragma unroll
            for (int mt = 0; mt < 4; mt++) {
                int ar = wm + mt * 16 + ((lmat & 1) << 3) + lane8;
                int ac = (ks << 1) + (lmat >> 1);
                uint32_t addr = sA + (uint32_t)((ar << 7) + ((ac ^ (ar & 7)) << 4));
                asm volatile("ldmatrix.sync.aligned.m8n8.x4.shared.b16 {%0,%1,%2,%3}, [%4];"
                             : "=r"(a[mt][0]), "=r"(a[mt][1]),
                               "=r"(a[mt][2]), "=r"(a[mt][3]) : "r"(addr));
            }
            uint32_t b[4][2];
#pragma unroll
            for (int np = 0; np < 2; np++) {
                int br = wn + np * 16 + ((lmat >> 1) << 3) + lane8;
                int bc = (ks << 1) + (lmat & 1);
                uint32_t addr = sB + (uint32_t)((br << 7) + ((bc ^ (br & 7)) << 4));
                asm volatile("ldmatrix.sync.aligned.m8n8.x4.shared.b16 {%0,%1,%2,%3}, [%4];"
                             : "=r"(b[np*2][0]), "=r"(b[np*2][1]),
                               "=r"(b[np*2+1][0]), "=r"(b[np*2+1][1]) : "r"(addr));
            }
#pragma unroll
            for (int mt = 0; mt < 4; mt++)
#pragma unroll
                for (int nt = 0; nt < 4; nt++) {
                    asm volatile(
                        "mma.sync.aligned.m16n8k16.row.col.f32.bf16.bf16.f32 "
                        "{%0,%1,%2,%3}, {%4,%5,%6,%7}, {%8,%9}, {%0,%1,%2,%3};"
                        : "+f"(c[mt][nt][0]), "+f"(c[mt][nt][1]),
                          "+f"(c[mt][nt][2]), "+f"(c[mt][nt][3])
                        : "r"(a[mt][0]), "r"(a[mt][1]), "r"(a[mt][2]), "r"(a[mt][3]),
                          "r"(b[nt][0]), "r"(b[nt][1]));
                }
        }
        __syncthreads();
    }

    // ---- epilogue ----
    float* C = (float*)Cv + (size_t)blockIdx.z * cspan;
    bf16*  Cb = (bf16*)Cv;
#pragma unroll
    for (int mt = 0; mt < 4; mt++) {
#pragma unroll
        for (int nt = 0; nt < 4; nt++) {
            int m = m0 + wm + mt * 16 + (lane >> 2);
            int n = n0 + wn + nt * 8 + 2 * (lane & 3);
#pragma unroll
            for (int half = 0; half < 2; half++) {
                int mm = m + half * 8;
                if (mm >= M || n >= N) continue;
                float v0 = c[mt][nt][half * 2];
                float v1 = c[mt][nt][half * 2 + 1];
                if (epi == 3) {
                    *(__nv_bfloat162*)(Cb + (size_t)mm * ldc + n) =
                        __floats2bfloat162_rn(v0, v1);
                    continue;
                }
                if (epi == 5) {
                    float* Cp = (float*)Cv;
                    Cp[((size_t)mm * ldc + n) * 2]     = softplusf(v0 + bias[n]);
                    Cp[((size_t)mm * ldc + n + 1) * 2] = softplusf(v1 + bias[n + 1]);
                    continue;
                }
                if (epi == 2) {
                    const float2 rv = *(const float2*)(resid + (size_t)mm * ldc + n);
                    v0 += rv.x; v1 += rv.y;
                }
                *(float2*)(C + (size_t)mm * ldc + n) = make_float2(v0, v1);
            }
        }
    }
}

// ---------------- split-K reduction for GEMM2 --------------------------------
__global__ void reduce_part_k() {
    int i = blockIdx.x * blockDim.x + threadIdx.x;
    if (i >= MROWS * DBC_W) return;
    float s = 0.f;
#pragma unroll
    for (int p = 0; p < KSPLIT; p++) s += g_part[(size_t)p * MROWS * DBC_W + i];
    int row = i / DBC_W, col = i % DBC_W;
    if (col < RK) {
        g_dbc_bf[i] = __float2bfloat16(s);
    } else if (col < RK + NST) {
        g_bc[(size_t)row * 32 + (col - RK) * 2] = s;
    } else {
        g_bc[(size_t)row * 32 + (col - RK - NST) * 2 + 1] = s;
    }
}

// ---------------- causal depthwise conv1d (k=4) + SiLU, 2-wide ---------------
__global__ void conv_silu_k(const float* __restrict__ cw, const float* __restrict__ cb) {
    int idx = blockIdx.x * blockDim.x + threadIdx.x;
    if (idx >= MROWS * DI / 2) return;
    int d2 = idx % (DI / 2);
    int d = d2 * 2;
    int l = (idx / (DI / 2)) % LSEQ;
    int b = idx / ((DI / 2) * LSEQ);
    float ax = cb[d], ay = cb[d + 1];
#pragma unroll
    for (int k = 0; k < 4; k++) {
        int ls = l - 3 + k;
        if (ls >= 0) {
            __nv_bfloat162 xv = *(const __nv_bfloat162*)
                (g_xz_bf + ((size_t)(b * LSEQ + ls)) * (2 * DI) + d);
            ax = fmaf(__bfloat162float(xv.x), cw[d * 4 + k], ax);
            ay = fmaf(__bfloat162float(xv.y), cw[(d + 1) * 4 + k], ay);
        }
    }
    float vx = siluf(ax), vy = siluf(ay);
    size_t e = (size_t)idx * 2;
    g_dxc[e * 2 + 1] = vx;
    g_dxc[e * 2 + 3] = vy;
    *(__nv_bfloat162*)(g_xc_bf + e) = __floats2bfloat162_rn(vx, vy);
}

// ---------------- selective scan: 2 states/thread, paired smem pipeline ------
// CTA: 128 threads = 16 d-channels x 8 threads (each thread: states n, n+8).
__device__ __forceinline__ void scan_fill(uint32_t sdx, uint32_t sbc, uint32_t sz,
                                          int tid, size_t bL, int l0, int d0) {
#pragma unroll
    for (int i = 0; i < 4; i++) {        // dx: 64 rows x 128B (16 (dt,xc) pairs)
        int idx = tid + i * 128;
        int r = idx >> 3, sg = idx & 7;
        cp16(sdx + (uint32_t)(r * 128 + sg * 16),
             g_dxc + ((bL + l0 + r) * DI + d0) * 2 + sg * 4, true);
    }
#pragma unroll
    for (int i = 0; i < 4; i++) {        // bc: 64 rows x 128B (16 (B,C) pairs)
        int idx = tid + i * 128;
        int r = idx >> 3, sg = idx & 7;
        cp16(sbc + (uint32_t)(r * 128 + sg * 16),
             g_bc + (bL + l0 + r) * 32 + sg * 4, true);
    }
    {                                    // z: 64 rows x 32B bf16
        int r = tid >> 1, sg = tid & 1;
        cp16(sz + (uint32_t)(r * 32 + sg * 16),
             g_xz_bf + (bL + l0 + r) * (2 * DI) + DI + d0 + sg * 8, true);
    }
}

__global__ __launch_bounds__(128) void scan_k(const float* __restrict__ A_log,
                                              const float* __restrict__ Dw) {
    __shared__ float s_dx[2][SCH * 32];
    __shared__ float s_bc[2][SCH * 32];
    __shared__ bf16  s_z [2][SCH * 16];
    __shared__ float s_y [SCH * 16];

    const int tid = threadIdx.x;
    const int nn = tid & 7;              // state pair (nn, nn+8)
    const int g  = tid >> 3;             // d-channel 0..15
    const int b  = blockIdx.x >> 7;      // 128 CTAs per batch
    const int d0 = (blockIdx.x & 127) << 4;
    const int d  = d0 + g;
    const size_t bL = (size_t)b * LSEQ;

    const float A0 = -__expf(A_log[d * NST + nn]);
    const float A1 = -__expf(A_log[d * NST + nn + 8]);
    const float Dd = Dw[d];
    float h0 = 0.f, h1 = 0.f;

    const uint32_t adx0 = (uint32_t)__cvta_generic_to_shared(&s_dx[0][0]);
    const uint32_t adx1 = (uint32_t)__cvta_generic_to_shared(&s_dx[1][0]);
    const uint32_t abc0 = (uint32_t)__cvta_generic_to_shared(&s_bc[0][0]);
    const uint32_t abc1 = (uint32_t)__cvta_generic_to_shared(&s_bc[1][0]);
    const uint32_t az0  = (uint32_t)__cvta_generic_to_shared(&s_z[0][0]);
    const uint32_t az1  = (uint32_t)__cvta_generic_to_shared(&s_z[1][0]);

    scan_fill(adx0, abc0, az0, tid, bL, 0, d0);
    asm volatile("cp.async.commit_group;" ::: "memory");

    const int NCH = LSEQ / SCH;
    for (int c = 0; c < NCH; c++) {
        const int buf = c & 1;
        if (c + 1 < NCH) {
            if (buf == 0) scan_fill(adx1, abc1, az1, tid, bL, (c + 1) * SCH, d0);
            else          scan_fill(adx0, abc0, az0, tid, bL, (c + 1) * SCH, d0);
            asm volatile("cp.async.commit_group;" ::: "memory");
            asm volatile("cp.async.wait_group 1;" ::: "memory");
        } else {
            asm volatile("cp.async.wait_group 0;" ::: "memory");
        }
        __syncthreads();

        const float* dx_ = s_dx[buf];
        const float* bc_ = s_bc[buf];

#pragma unroll 4
        for (int l = 0; l < SCH; l++) {
            float2 dx = *(const float2*)(dx_ + l * 32 + g * 2);        // (dt, xc)
            float2 b0 = *(const float2*)(bc_ + l * 32 + nn * 2);       // (B, C) state nn
            float2 b1 = *(const float2*)(bc_ + l * 32 + nn * 2 + 16);  // state nn+8

            float bx = dx.x * dx.y;
            h0 = fmaf(__expf(dx.x * A0), h0, bx * b0.x);
            h1 = fmaf(__expf(dx.x * A1), h1, bx * b1.x);

            float y = fmaf(h1, b1.y, h0 * b0.y);
            y += __shfl_xor_sync(0xffffffffu, y, 4);
            y += __shfl_xor_sync(0xffffffffu, y, 2);
            y += __shfl_xor_sync(0xffffffffu, y, 1);

            if (nn == 0) s_y[l * 16 + g] = fmaf(Dd, dx.y, y);
        }
        __syncthreads();

        const bf16* z_ = s_z[buf];
        const int l0 = c * SCH;
#pragma unroll
        for (int i = tid; i < SCH * 16; i += 128) {
            int r = i >> 4, gg = i & 15;
            float zv = __bfloat162float(z_[i]);
            g_u_bf[(bL + l0 + r) * DI + d0 + gg] =
                __float2bfloat16(s_y[i] * siluf(zv));
        }
    }
}

// ---------------- host orchestration ----------------------------------------
extern "C" void kernel_launch(void* const* d_in, const int* in_sizes, int n_in,
                              void* d_out, int out_size) {
    const float* x      = (const float*)d_in[0];
    const float* norm_w = (const float*)d_in[1];
    const float* W_in   = (const float*)d_in[2];
    const float* conv_w = (const float*)d_in[3];
    const float* conv_b = (const float*)d_in[4];
    const float* W_x    = (const float*)d_in[5];
    const float* W_dt   = (const float*)d_in[6];
    const float* b_dt   = (const float*)d_in[7];
    const float* A_log  = (const float*)d_in[8];
    const float* Dpar   = (const float*)d_in[9];
    const float* W_out  = (const float*)d_in[10];
    float* out = (float*)d_out;

    float *px, *ppart, *pdxc;
    bf16 *pxz_bf, *ph_bf, *pxc_bf, *pdbc_bf, *pu_bf, *pWin, *pWx, *pWdt, *pWout;
    cudaGetSymbolAddress((void**)&px,     g_x);
    cudaGetSymbolAddress((void**)&ppart,  g_part);
    cudaGetSymbolAddress((void**)&pdxc,   g_dxc);
    cudaGetSymbolAddress((void**)&pxz_bf, g_xz_bf);
    cudaGetSymbolAddress((void**)&ph_bf,  g_h_bf);
    cudaGetSymbolAddress((void**)&pxc_bf, g_xc_bf);
    cudaGetSymbolAddress((void**)&pdbc_bf,g_dbc_bf);
    cudaGetSymbolAddress((void**)&pu_bf,  g_u_bf);
    cudaGetSymbolAddress((void**)&pWin,   g_Win_bf);
    cudaGetSymbolAddress((void**)&pWx,    g_Wx_bf);
    cudaGetSymbolAddress((void**)&pWdt,   g_Wdt_bf);
    cudaGetSymbolAddress((void**)&pWout,  g_Wout_bf);

    const int M = MROWS;
    const int GSMEM = 2 * (int)STAGEB;
    cudaFuncSetAttribute(bf16gemm_nt_k,
                         cudaFuncAttributeMaxDynamicSharedMemorySize, GSMEM);

    dim3 thr(256);

    f2bf2_k<<<1480, 256>>>((const float4*)W_in,  (__nv_bfloat162*)pWin,  NL * 2 * DI * DM / 4,
                           (const float4*)W_x,   (__nv_bfloat162*)pWx,   NL * DBC_W * DI / 4);
    f2bf2_k<<<1480, 256>>>((const float4*)W_dt,  (__nv_bfloat162*)pWdt,  NL * DI * RK / 4,
                           (const float4*)W_out, (__nv_bfloat162*)pWout, NL * DM * DI / 4);

    for (int l = 0; l < NL; l++) {
        const float* xres = (l == 0) ? x : px;

        rmsnorm_k<<<M, 256>>>(xres, norm_w + (size_t)l * DM);

        // 2) xz = h @ W_in^T -> bf16
        {
            dim3 g(2 * DI / 128, M / 128, 1);
            bf16gemm_nt_k<<<g, thr, GSMEM>>>(ph_bf, DM, pWin + (size_t)l * 2 * DI * DM, DM,
                                             pxz_bf, 2 * DI, nullptr, nullptr,
                                             M, 2 * DI, DM, 3, 0, 0);
        }

        conv_silu_k<<<(MROWS*DI/2 + 255) / 256, 256>>>(
            conv_w + (size_t)l * DI * 4, conv_b + (size_t)l * DI);

        // 4) dbc = xc @ W_x^T  split-K=8 + reduce (dt_low bf16 + (B,C) pairs)
        {
            const int Kc = DI / KSPLIT;
            dim3 g(1, M / 128, KSPLIT);
            bf16gemm_nt_k<<<g, thr, GSMEM>>>(pxc_bf, DI, pWx + (size_t)l * DBC_W * DI, DI,
                                             ppart, DBC_W, nullptr, nullptr,
                                             M, DBC_W, Kc, 0,
                                             Kc, (size_t)M * DBC_W);
            reduce_part_k<<<(MROWS * DBC_W + 255) / 256, 256>>>();
        }

        // 5) delta = softplus(dt_low @ W_dt^T + b_dt) -> pair slot 0 of g_dxc
        {
            dim3 g(DI / 128, M / 128, 1);
            bf16gemm_nt_k<<<g, thr, GSMEM>>>(pdbc_bf, DBC_W, pWdt + (size_t)l * DI * RK, RK,
                                             pdxc, DI, b_dt + (size_t)l * DI, nullptr,
                                             M, DI, RK, 5, 0, 0);
        }

        // 6) selective scan (2 states/thread)
        scan_k<<<BATCH * (DI / 16), 128>>>(
            A_log + (size_t)l * DI * NST, Dpar + (size_t)l * DI);

        // 7) x_next = xres + u @ W_out^T (fused residual, M128 — best measured)
        {
            float* Cout = (l == NL - 1) ? out : px;
            dim3 g(DM / 128, M / 128, 1);
            bf16gemm_nt_k<<<g, thr, GSMEM>>>(pu_bf, DI, pWout + (size_t)l * DM * DI, DI,
                                             Cout, DM, nullptr, xres,
                                             M, DM, DI, 2, 0, 0);
        }
    }
}

// round 15
// speedup vs baseline: 1.0482x; 1.0004x over previous
#include <cuda_runtime.h>
#include <cuda_bf16.h>
#include <math.h>
#include <stdint.h>

#define BATCH 2
#define LSEQ  1024
#define DM    1024
#define DI    2048
#define NST   16
#define RK    64
#define DBC_W (RK + 2*NST)   /* 96 */
#define NL    4
#define MROWS (BATCH*LSEQ)   /* 2048 */
#define KSPLIT 8
#define SCH   64             /* scan chunk (timesteps) */

typedef __nv_bfloat16 bf16;

// ---------------- fp32 scratch ----------------------------------------------
__device__ float g_x    [MROWS*DM];
__device__ float g_dxc  [MROWS*DI*2];    // interleaved (delta, xc) pairs
__device__ float g_bc   [MROWS*32];      // interleaved (B, C) pairs per state
__device__ float g_part [KSPLIT*MROWS*DBC_W];

// ---------------- bf16 scratch ------------------------------------------------
__device__ bf16 g_xz_bf [MROWS*2*DI];
__device__ bf16 g_h_bf  [MROWS*DM];
__device__ bf16 g_xc_bf [MROWS*DI];
__device__ bf16 g_dbc_bf[MROWS*DBC_W];
__device__ bf16 g_u_bf  [MROWS*DI];
__device__ bf16 g_Win_bf [NL*2*DI*DM];
__device__ bf16 g_Wx_bf  [NL*DBC_W*DI];
__device__ bf16 g_Wdt_bf [NL*DI*RK];
__device__ bf16 g_Wout_bf[NL*DM*DI];

// ---------------- helpers ---------------------------------------------------
__device__ __forceinline__ float siluf(float v) { return v / (1.f + __expf(-v)); }
__device__ __forceinline__ float softplusf(float v) {
    return (v > 20.f) ? v : log1pf(__expf(v));
}
__device__ __forceinline__ void cp16(uint32_t s, const void* g, bool pred) {
    if (pred)
        asm volatile("cp.async.cg.shared.global [%0], [%1], 16;" :: "r"(s), "l"(g));
    else
        asm volatile("cp.async.cg.shared.global [%0], [%1], 16, 0;" :: "r"(s), "l"(g));
}

// ---------------- dual fp32 -> bf16 convert ----------------------------------
__global__ void f2bf2_k(const float4* __restrict__ s1, __nv_bfloat162* __restrict__ d1, int n41,
                        const float4* __restrict__ s2, __nv_bfloat162* __restrict__ d2, int n42) {
    int i = blockIdx.x * blockDim.x + threadIdx.x;
    int tot = n41 + n42;
    for (; i < tot; i += gridDim.x * blockDim.x) {
        if (i < n41) {
            float4 v = s1[i];
            d1[2*i]   = __floats2bfloat162_rn(v.x, v.y);
            d1[2*i+1] = __floats2bfloat162_rn(v.z, v.w);
        } else {
            int j = i - n41;
            float4 v = s2[j];
            d2[2*j]   = __floats2bfloat162_rn(v.x, v.y);
            d2[2*j+1] = __floats2bfloat162_rn(v.z, v.w);
        }
    }
}

// ---------------- RMSNorm -----------------------------------------------------
__global__ void rmsnorm_k(const float* __restrict__ xin, const float* __restrict__ w) {
    int row = blockIdx.x;
    const float4* xr = (const float4*)(xin + (size_t)row * DM);
    __shared__ float red[8];
    float4 v = xr[threadIdx.x];
    float s = v.x*v.x + v.y*v.y + v.z*v.z + v.w*v.w;
#pragma unroll
    for (int off = 16; off > 0; off >>= 1) s += __shfl_xor_sync(0xffffffffu, s, off);
    if ((threadIdx.x & 31) == 0) red[threadIdx.x >> 5] = s;
    __syncthreads();
    float tot = red[0] + red[1] + red[2] + red[3] + red[4] + red[5] + red[6] + red[7];
    float inv = rsqrtf(tot * (1.f / DM) + 1e-5f);
    const float4 wv = ((const float4*)w)[threadIdx.x];
    __nv_bfloat162* hr = (__nv_bfloat162*)(g_h_bf + (size_t)row * DM);
    hr[2*threadIdx.x]   = __floats2bfloat162_rn(v.x * inv * wv.x, v.y * inv * wv.y);
    hr[2*threadIdx.x+1] = __floats2bfloat162_rn(v.z * inv * wv.z, v.w * inv * wv.w);
}

// ---------------- bf16 tensor-core NT GEMM (M-tile 128) ----------------------
// epi: 0 fp32 plain, 2 fp32 acc+resid, 3 bf16 plain,
//      5 softplus(acc+bias[n]) -> stride-2 store into pair buffer slot 0
#define STAGEB 32768u
__global__ __launch_bounds__(256, 2) void bf16gemm_nt_k(
    const bf16* __restrict__ A, int lda,
    const bf16* __restrict__ B, int ldb,
    void* __restrict__ Cv, int ldc,
    const float* __restrict__ bias,
    const float* __restrict__ resid,
    int M, int N, int K, int epi,
    int kspan, size_t cspan)
{
    extern __shared__ char smem[];
    A += (size_t)blockIdx.z * kspan;
    B += (size_t)blockIdx.z * kspan;

    const int tid  = threadIdx.x;
    const int warp = tid >> 5;
    const int lane = tid & 31;
    const int m0 = blockIdx.y * 128;
    const int n0 = blockIdx.x * 128;
    const int wm = (warp >> 2) * 64;
    const int wn = (warp & 3) * 32;

    float c[4][4][4];
#pragma unroll
    for (int i = 0; i < 4; i++)
#pragma unroll
        for (int j = 0; j < 4; j++)
#pragma unroll
            for (int r = 0; r < 4; r++) c[i][j][r] = 0.f;

    const uint32_t sbase = (uint32_t)__cvta_generic_to_shared(smem);
    const int nk = K >> 6;
    const int lane8 = lane & 7;
    const int lmat  = lane >> 3;

    {
#pragma unroll
        for (int i = 0; i < 4; i++) {
            int idx = tid + i * 256;
            int r = idx >> 3, cc = idx & 7;
            uint32_t so = (uint32_t)((r << 7) + ((cc ^ (r & 7)) << 4));
            cp16(sbase + so,          A + (size_t)(m0 + r) * lda + cc * 8, (m0 + r) < M);
            cp16(sbase + 16384u + so, B + (size_t)(n0 + r) * ldb + cc * 8, (n0 + r) < N);
        }
        asm volatile("cp.async.commit_group;" ::: "memory");
    }

    for (int kt = 0; kt < nk; kt++) {
        const uint32_t st = (uint32_t)(kt & 1) * STAGEB;
        if (kt + 1 < nk) {
            const int k0 = (kt + 1) << 6;
            const uint32_t st1 = (uint32_t)((kt + 1) & 1) * STAGEB;
#pragma unroll
            for (int i = 0; i < 4; i++) {
                int idx = tid + i * 256;
                int r = idx >> 3, cc = idx & 7;
                uint32_t so = st1 + (uint32_t)((r << 7) + ((cc ^ (r & 7)) << 4));
                cp16(sbase + so,          A + (size_t)(m0 + r) * lda + k0 + cc * 8, (m0 + r) < M);
                cp16(sbase + 16384u + so, B + (size_t)(n0 + r) * ldb + k0 + cc * 8, (n0 + r) < N);
            }
            asm volatile("cp.async.commit_group;" ::: "memory");
            asm volatile("cp.async.wait_group 1;" ::: "memory");
        } else {
            asm volatile("cp.async.wait_group 0;" ::: "memory");
        }
        __syncthreads();

        const uint32_t sA = sbase + st;
        const uint32_t sB = sA + 16384u;

#pragma unroll
        for (int ks = 0; ks < 4; ks++) {
            uint32_t a[4][4];
#pragma unroll
            for (int mt = 0; mt < 4; mt++) {
                int ar = wm + mt * 16 + ((lmat & 1) << 3) + lane8;
                int ac = (ks << 1) + (lmat >> 1);
                uint32_t addr = sA + (uint32_t)((ar << 7) + ((ac ^ (ar & 7)) << 4));
                asm volatile("ldmatrix.sync.aligned.m8n8.x4.shared.b16 {%0,%1,%2,%3}, [%4];"
                             : "=r"(a[mt][0]), "=r"(a[mt][1]),
                               "=r"(a[mt][2]), "=r"(a[mt][3]) : "r"(addr));
            }
            uint32_t b[4][2];
#pragma unroll
            for (int np = 0; np < 2; np++) {
                int br = wn + np * 16 + ((lmat >> 1) << 3) + lane8;
                int bc = (ks << 1) + (lmat & 1);
                uint32_t addr = sB + (uint32_t)((br << 7) + ((bc ^ (br & 7)) << 4));
                asm volatile("ldmatrix.sync.aligned.m8n8.x4.shared.b16 {%0,%1,%2,%3}, [%4];"
                             : "=r"(b[np*2][0]), "=r"(b[np*2][1]),
                               "=r"(b[np*2+1][0]), "=r"(b[np*2+1][1]) : "r"(addr));
            }
#pragma unroll
            for (int mt = 0; mt < 4; mt++)
#pragma unroll
                for (int nt = 0; nt < 4; nt++) {
                    asm volatile(
                        "mma.sync.aligned.m16n8k16.row.col.f32.bf16.bf16.f32 "
                        "{%0,%1,%2,%3}, {%4,%5,%6,%7}, {%8,%9}, {%0,%1,%2,%3};"
                        : "+f"(c[mt][nt][0]), "+f"(c[mt][nt][1]),
                          "+f"(c[mt][nt][2]), "+f"(c[mt][nt][3])
                        : "r"(a[mt][0]), "r"(a[mt][1]), "r"(a[mt][2]), "r"(a[mt][3]),
                          "r"(b[nt][0]), "r"(b[nt][1]));
                }
        }
        __syncthreads();
    }

    // ---- epilogue ----
    float* C = (float*)Cv + (size_t)blockIdx.z * cspan;
    bf16*  Cb = (bf16*)Cv;
#pragma unroll
    for (int mt = 0; mt < 4; mt++) {
#pragma unroll
        for (int nt = 0; nt < 4; nt++) {
            int m = m0 + wm + mt * 16 + (lane >> 2);
            int n = n0 + wn + nt * 8 + 2 * (lane & 3);
#pragma unroll
            for (int half = 0; half < 2; half++) {
                int mm = m + half * 8;
                if (mm >= M || n >= N) continue;
                float v0 = c[mt][nt][half * 2];
                float v1 = c[mt][nt][half * 2 + 1];
                if (epi == 3) {
                    *(__nv_bfloat162*)(Cb + (size_t)mm * ldc + n) =
                        __floats2bfloat162_rn(v0, v1);
                    continue;
                }
                if (epi == 5) {
                    float* Cp = (float*)Cv;
                    Cp[((size_t)mm * ldc + n) * 2]     = softplusf(v0 + bias[n]);
                    Cp[((size_t)mm * ldc + n + 1) * 2] = softplusf(v1 + bias[n + 1]);
                    continue;
                }
                if (epi == 2) {
                    const float2 rv = *(const float2*)(resid + (size_t)mm * ldc + n);
                    v0 += rv.x; v1 += rv.y;
                }
                *(float2*)(C + (size_t)mm * ldc + n) = make_float2(v0, v1);
            }
        }
    }
}

// ---------------- split-K reduction for GEMM2 --------------------------------
__global__ void reduce_part_k() {
    int i = blockIdx.x * blockDim.x + threadIdx.x;
    if (i >= MROWS * DBC_W) return;
    float s = 0.f;
#pragma unroll
    for (int p = 0; p < KSPLIT; p++) s += g_part[(size_t)p * MROWS * DBC_W + i];
    int row = i / DBC_W, col = i % DBC_W;
    if (col < RK) {
        g_dbc_bf[i] = __float2bfloat16(s);
    } else if (col < RK + NST) {
        g_bc[(size_t)row * 32 + (col - RK) * 2] = s;
    } else {
        g_bc[(size_t)row * 32 + (col - RK - NST) * 2 + 1] = s;
    }
}

// ---------------- causal depthwise conv1d (k=4) + SiLU, 2-wide ---------------
__global__ void conv_silu_k(const float* __restrict__ cw, const float* __restrict__ cb) {
    int idx = blockIdx.x * blockDim.x + threadIdx.x;
    if (idx >= MROWS * DI / 2) return;
    int d2 = idx % (DI / 2);
    int d = d2 * 2;
    int l = (idx / (DI / 2)) % LSEQ;
    int b = idx / ((DI / 2) * LSEQ);
    float ax = cb[d], ay = cb[d + 1];
#pragma unroll
    for (int k = 0; k < 4; k++) {
        int ls = l - 3 + k;
        if (ls >= 0) {
            __nv_bfloat162 xv = *(const __nv_bfloat162*)
                (g_xz_bf + ((size_t)(b * LSEQ + ls)) * (2 * DI) + d);
            ax = fmaf(__bfloat162float(xv.x), cw[d * 4 + k], ax);
            ay = fmaf(__bfloat162float(xv.y), cw[(d + 1) * 4 + k], ay);
        }
    }
    float vx = siluf(ax), vy = siluf(ay);
    size_t e = (size_t)idx * 2;
    g_dxc[e * 2 + 1] = vx;
    g_dxc[e * 2 + 3] = vy;
    *(__nv_bfloat162*)(g_xc_bf + e) = __floats2bfloat162_rn(vx, vy);
}

// ---------------- selective scan: 2 states/thread, paired smem pipeline ------
// CTA: 128 threads = 16 d-channels x 8 threads (each thread: states n, n+8).
__device__ __forceinline__ void scan_fill(uint32_t sdx, uint32_t sbc, uint32_t sz,
                                          int tid, size_t bL, int l0, int d0) {
#pragma unroll
    for (int i = 0; i < 4; i++) {        // dx: 64 rows x 128B (16 (dt,xc) pairs)
        int idx = tid + i * 128;
        int r = idx >> 3, sg = idx & 7;
        cp16(sdx + (uint32_t)(r * 128 + sg * 16),
             g_dxc + ((bL + l0 + r) * DI + d0) * 2 + sg * 4, true);
    }
#pragma unroll
    for (int i = 0; i < 4; i++) {        // bc: 64 rows x 128B (16 (B,C) pairs)
        int idx = tid + i * 128;
        int r = idx >> 3, sg = idx & 7;
        cp16(sbc + (uint32_t)(r * 128 + sg * 16),
             g_bc + (bL + l0 + r) * 32 + sg * 4, true);
    }
    {                                    // z: 64 rows x 32B bf16
        int r = tid >> 1, sg = tid & 1;
        cp16(sz + (uint32_t)(r * 32 + sg * 16),
             g_xz_bf + (bL + l0 + r) * (2 * DI) + DI + d0 + sg * 8, true);
    }
}

__global__ __launch_bounds__(128) void scan_k(const float* __restrict__ A_log,
                                              const float* __restrict__ Dw) {
    __shared__ float s_dx[2][SCH * 32];
    __shared__ float s_bc[2][SCH * 32];
    __shared__ bf16  s_z [2][SCH * 16];
    __shared__ float s_y [SCH * 16];

    const int tid = threadIdx.x;
    const int nn = tid & 7;              // state pair (nn, nn+8)
    const int g  = tid >> 3;             // d-channel 0..15
    const int b  = blockIdx.x >> 7;      // 128 CTAs per batch
    const int d0 = (blockIdx.x & 127) << 4;
    const int d  = d0 + g;
    const size_t bL = (size_t)b * LSEQ;

    const float A0 = -__expf(A_log[d * NST + nn]);
    const float A1 = -__expf(A_log[d * NST + nn + 8]);
    const float Dd = Dw[d];
    float h0 = 0.f, h1 = 0.f;

    const uint32_t adx0 = (uint32_t)__cvta_generic_to_shared(&s_dx[0][0]);
    const uint32_t adx1 = (uint32_t)__cvta_generic_to_shared(&s_dx[1][0]);
    const uint32_t abc0 = (uint32_t)__cvta_generic_to_shared(&s_bc[0][0]);
    const uint32_t abc1 = (uint32_t)__cvta_generic_to_shared(&s_bc[1][0]);
    const uint32_t az0  = (uint32_t)__cvta_generic_to_shared(&s_z[0][0]);
    const uint32_t az1  = (uint32_t)__cvta_generic_to_shared(&s_z[1][0]);

    scan_fill(adx0, abc0, az0, tid, bL, 0, d0);
    asm volatile("cp.async.commit_group;" ::: "memory");

    const int NCH = LSEQ / SCH;
    for (int c = 0; c < NCH; c++) {
        const int buf = c & 1;
        if (c + 1 < NCH) {
            if (buf == 0) scan_fill(adx1, abc1, az1, tid, bL, (c + 1) * SCH, d0);
            else          scan_fill(adx0, abc0, az0, tid, bL, (c + 1) * SCH, d0);
            asm volatile("cp.async.commit_group;" ::: "memory");
            asm volatile("cp.async.wait_group 1;" ::: "memory");
        } else {
            asm volatile("cp.async.wait_group 0;" ::: "memory");
        }
        __syncthreads();

        const float* dx_ = s_dx[buf];
        const float* bc_ = s_bc[buf];

#pragma unroll 4
        for (int l = 0; l < SCH; l++) {
            float2 dx = *(const float2*)(dx_ + l * 32 + g * 2);        // (dt, xc)
            float2 b0 = *(const float2*)(bc_ + l * 32 + nn * 2);       // (B, C) state nn
            float2 b1 = *(const float2*)(bc_ + l * 32 + nn * 2 + 16);  // state nn+8

            float bx = dx.x * dx.y;
            h0 = fmaf(__expf(dx.x * A0), h0, bx * b0.x);
            h1 = fmaf(__expf(dx.x * A1), h1, bx * b1.x);

            float y = fmaf(h1, b1.y, h0 * b0.y);
            y += __shfl_xor_sync(0xffffffffu, y, 4);
            y += __shfl_xor_sync(0xffffffffu, y, 2);
            y += __shfl_xor_sync(0xffffffffu, y, 1);

            if (nn == 0) s_y[l * 16 + g] = fmaf(Dd, dx.y, y);
        }
        __syncthreads();

        const bf16* z_ = s_z[buf];
        const int l0 = c * SCH;
#pragma unroll
        for (int i = tid; i < SCH * 16; i += 128) {
            int r = i >> 4, gg = i & 15;
            float zv = __bfloat162float(z_[i]);
            g_u_bf[(bL + l0 + r) * DI + d0 + gg] =
                __float2bfloat16(s_y[i] * siluf(zv));
        }
    }
}

// ---------------- host orchestration ----------------------------------------
extern "C" void kernel_launch(void* const* d_in, const int* in_sizes, int n_in,
                              void* d_out, int out_size) {
    const float* x      = (const float*)d_in[0];
    const float* norm_w = (const float*)d_in[1];
    const float* W_in   = (const float*)d_in[2];
    const float* conv_w = (const float*)d_in[3];
    const float* conv_b = (const float*)d_in[4];
    const float* W_x    = (const float*)d_in[5];
    const float* W_dt   = (const float*)d_in[6];
    const float* b_dt   = (const float*)d_in[7];
    const float* A_log  = (const float*)d_in[8];
    const float* Dpar   = (const float*)d_in[9];
    const float* W_out  = (const float*)d_in[10];
    float* out = (float*)d_out;

    float *px, *ppart, *pdxc;
    bf16 *pxz_bf, *ph_bf, *pxc_bf, *pdbc_bf, *pu_bf, *pWin, *pWx, *pWdt, *pWout;
    cudaGetSymbolAddress((void**)&px,     g_x);
    cudaGetSymbolAddress((void**)&ppart,  g_part);
    cudaGetSymbolAddress((void**)&pdxc,   g_dxc);
    cudaGetSymbolAddress((void**)&pxz_bf, g_xz_bf);
    cudaGetSymbolAddress((void**)&ph_bf,  g_h_bf);
    cudaGetSymbolAddress((void**)&pxc_bf, g_xc_bf);
    cudaGetSymbolAddress((void**)&pdbc_bf,g_dbc_bf);
    cudaGetSymbolAddress((void**)&pu_bf,  g_u_bf);
    cudaGetSymbolAddress((void**)&pWin,   g_Win_bf);
    cudaGetSymbolAddress((void**)&pWx,    g_Wx_bf);
    cudaGetSymbolAddress((void**)&pWdt,   g_Wdt_bf);
    cudaGetSymbolAddress((void**)&pWout,  g_Wout_bf);

    const int M = MROWS;
    const int GSMEM = 2 * (int)STAGEB;
    cudaFuncSetAttribute(bf16gemm_nt_k,
                         cudaFuncAttributeMaxDynamicSharedMemorySize, GSMEM);

    dim3 thr(256);

    f2bf2_k<<<1480, 256>>>((const float4*)W_in,  (__nv_bfloat162*)pWin,  NL * 2 * DI * DM / 4,
                           (const float4*)W_x,   (__nv_bfloat162*)pWx,   NL * DBC_W * DI / 4);
    f2bf2_k<<<1480, 256>>>((const float4*)W_dt,  (__nv_bfloat162*)pWdt,  NL * DI * RK / 4,
                           (const float4*)W_out, (__nv_bfloat162*)pWout, NL * DM * DI / 4);

    for (int l = 0; l < NL; l++) {
        const float* xres = (l == 0) ? x : px;

        rmsnorm_k<<<M, 256>>>(xres, norm_w + (size_t)l * DM);

        // 2) xz = h @ W_in^T -> bf16
        {
            dim3 g(2 * DI / 128, M / 128, 1);
            bf16gemm_nt_k<<<g, thr, GSMEM>>>(ph_bf, DM, pWin + (size_t)l * 2 * DI * DM, DM,
                                             pxz_bf, 2 * DI, nullptr, nullptr,
                                             M, 2 * DI, DM, 3, 0, 0);
        }

        conv_silu_k<<<(MROWS*DI/2 + 255) / 256, 256>>>(
            conv_w + (size_t)l * DI * 4, conv_b + (size_t)l * DI);

        // 4) dbc = xc @ W_x^T  split-K=8 + reduce (dt_low bf16 + (B,C) pairs)
        {
            const int Kc = DI / KSPLIT;
            dim3 g(1, M / 128, KSPLIT);
            bf16gemm_nt_k<<<g, thr, GSMEM>>>(pxc_bf, DI, pWx + (size_t)l * DBC_W * DI, DI,
                                             ppart, DBC_W, nullptr, nullptr,
                                             M, DBC_W, Kc, 0,
                                             Kc, (size_t)M * DBC_W);
            reduce_part_k<<<(MROWS * DBC_W + 255) / 256, 256>>>();
        }

        // 5) delta = softplus(dt_low @ W_dt^T + b_dt) -> pair slot 0 of g_dxc
        {
            dim3 g(DI / 128, M / 128, 1);
            bf16gemm_nt_k<<<g, thr, GSMEM>>>(pdbc_bf, DBC_W, pWdt + (size_t)l * DI * RK, RK,
                                             pdxc, DI, b_dt + (size_t)l * DI, nullptr,
                                             M, DI, RK, 5, 0, 0);
        }

        // 6) selective scan (2 states/thread)
        scan_k<<<BATCH * (DI / 16), 128>>>(
            A_log + (size_t)l * DI * NST, Dpar + (size_t)l * DI);

        // 7) x_next = xres + u @ W_out^T (fused residual, M128 — best measured)
        {
            float* Cout = (l == NL - 1) ? out : px;
            dim3 g(DM / 128, M / 128, 1);
            bf16gemm_nt_k<<<g, thr, GSMEM>>>(pu_bf, DI, pWout + (size_t)l * DM * DI, DI,
                                             Cout, DM, nullptr, xres,
                                             M, DM, DI, 2, 0, 0);
        }
    }
}